// round 1
// baseline (speedup 1.0000x reference)
#include <cuda_runtime.h>

static constexpr int HID = 2048;
static constexpr int HV4 = HID / 4;     // 512 float4 per row
static constexpr int NTHREADS = 512;    // one float4 per thread
static constexpr int NWARP = NTHREADS / 32;

__global__ __launch_bounds__(NTHREADS, 2)
void altup_kernel(const float* __restrict__ hs,    // [4, B*S, H]
                  const float* __restrict__ act,   // [B*S, H]
                  const float* __restrict__ rns,   // [H]
                  const float* __restrict__ rw,    // [H, 4]
                  const float* __restrict__ pw,    // [4, 16]
                  const float* __restrict__ cw,    // [4, 4]
                  const float* __restrict__ cosc,  // [H]
                  float* __restrict__ out,         // [4, B*S, H]
                  int n_tokens)
{
    __shared__ float red[NWARP][10];
    __shared__ float bc[20];            // raw[16], coef[4]

    const int tid  = threadIdx.x;
    const int lane = tid & 31;
    const int warp = tid >> 5;

    // ---- loop-invariant per-thread weights (channels 4*tid .. 4*tid+3) ----
    const float4 rsc = ((const float4*)rns)[tid];
    const float4* rw4 = (const float4*)rw;
    float4 w0 = rw4[4 * tid + 0];
    float4 w1 = rw4[4 * tid + 1];
    float4 w2 = rw4[4 * tid + 2];
    float4 w3 = rw4[4 * tid + 3];
    w0.x *= rsc.x; w0.y *= rsc.x; w0.z *= rsc.x; w0.w *= rsc.x;
    w1.x *= rsc.y; w1.y *= rsc.y; w1.z *= rsc.y; w1.w *= rsc.y;
    w2.x *= rsc.z; w2.y *= rsc.z; w2.z *= rsc.z; w2.w *= rsc.z;
    w3.x *= rsc.w; w3.y *= rsc.w; w3.z *= rsc.w; w3.w *= rsc.w;
    const float4 cs = ((const float4*)cosc)[tid];

    const size_t plane = (size_t)n_tokens * HV4;   // float4 stride between modalities
    const float4* hsv  = (const float4*)hs;
    const float4* actv = (const float4*)act;
    float4* outv = (float4*)out;

    for (int t = blockIdx.x; t < n_tokens; t += gridDim.x) {
        const size_t tb = (size_t)t * HV4 + tid;

        // Issue ALL global loads up front (x1..x3 only needed after the
        // reduction — their latency hides under the barriers).
        float4 x0 = hsv[tb];
        float4 x1 = hsv[plane + tb];
        float4 x2 = hsv[2 * plane + tb];
        float4 x3 = hsv[3 * plane + tb];
        float4 a  = actv[tb];

        // ---- 10 per-thread partials: sumsq(hs0), sumsq(act), 4+4 router dots ----
        float p[10];
        p[0] = x0.x*x0.x + x0.y*x0.y + x0.z*x0.z + x0.w*x0.w;
        p[1] = a.x*a.x + a.y*a.y + a.z*a.z + a.w*a.w;
        p[2] = x0.x*w0.x + x0.y*w1.x + x0.z*w2.x + x0.w*w3.x;
        p[3] = x0.x*w0.y + x0.y*w1.y + x0.z*w2.y + x0.w*w3.y;
        p[4] = x0.x*w0.z + x0.y*w1.z + x0.z*w2.z + x0.w*w3.z;
        p[5] = x0.x*w0.w + x0.y*w1.w + x0.z*w2.w + x0.w*w3.w;
        p[6] = a.x*w0.x + a.y*w1.x + a.z*w2.x + a.w*w3.x;
        p[7] = a.x*w0.y + a.y*w1.y + a.z*w2.y + a.w*w3.y;
        p[8] = a.x*w0.z + a.y*w1.z + a.z*w2.z + a.w*w3.z;
        p[9] = a.x*w0.w + a.y*w1.w + a.z*w2.w + a.w*w3.w;

        #pragma unroll
        for (int i = 0; i < 10; i++) {
            #pragma unroll
            for (int off = 16; off > 0; off >>= 1)
                p[i] += __shfl_xor_sync(0xffffffffu, p[i], off);
        }
        if (lane == 0) {
            #pragma unroll
            for (int i = 0; i < 10; i++) red[warp][i] = p[i];
        }
        __syncthreads();

        if (tid == 0) {
            float tot[10];
            #pragma unroll
            for (int i = 0; i < 10; i++) tot[i] = red[0][i];
            #pragma unroll
            for (int w = 1; w < NWARP; w++) {
                #pragma unroll
                for (int i = 0; i < 10; i++) tot[i] += red[w][i];
            }
            const float invH = 1.0f / (float)HID;
            const float ih = rsqrtf(tot[0] * invH + 1e-6f) * invH;
            const float ia = rsqrtf(tot[1] * invH + 1e-6f) * invH;
            float mp[4], mc[4];
            #pragma unroll
            for (int n = 0; n < 4; n++) {
                mp[n] = tanhf(tot[2 + n] * ih);
                mc[n] = tanhf(tot[6 + n] * ia);
            }
            #pragma unroll
            for (int m = 0; m < 4; m++) {
                #pragma unroll
                for (int n = 0; n < 4; n++) {
                    float r = 0.0f;
                    #pragma unroll
                    for (int k = 0; k < 4; k++) r += mp[k] * pw[k * 16 + m * 4 + n];
                    bc[m * 4 + n] = r;
                }
                float c = 1.0f;
                #pragma unroll
                for (int k = 0; k < 4; k++) c += mc[k] * cw[k * 4 + m];
                bc[16 + m] = c;
            }
        }
        __syncthreads();

        // ---- phase 2: mix, innovate, correct, scale, store ----
        // pred0 first (needed for innovation), then stream m = 0..3.
        float r00 = bc[0], r01 = bc[1], r02 = bc[2], r03 = bc[3];
        float4 p0;
        p0.x = x0.x + r00*x0.x + r01*x1.x + r02*x2.x + r03*x3.x;
        p0.y = x0.y + r00*x0.y + r01*x1.y + r02*x2.y + r03*x3.y;
        p0.z = x0.z + r00*x0.z + r01*x1.z + r02*x2.z + r03*x3.z;
        p0.w = x0.w + r00*x0.w + r01*x1.w + r02*x2.w + r03*x3.w;
        float4 inn;
        inn.x = a.x - p0.x; inn.y = a.y - p0.y; inn.z = a.z - p0.z; inn.w = a.w - p0.w;

        {   // m = 0
            float c = bc[16];
            float4 o;
            o.x = (p0.x + c * inn.x) * cs.x;
            o.y = (p0.y + c * inn.y) * cs.y;
            o.z = (p0.z + c * inn.z) * cs.z;
            o.w = (p0.w + c * inn.w) * cs.w;
            outv[tb] = o;
        }
        #pragma unroll
        for (int m = 1; m < 4; m++) {
            float rm0 = bc[m*4+0], rm1 = bc[m*4+1], rm2 = bc[m*4+2], rm3 = bc[m*4+3];
            float c = bc[16 + m];
            float4 xm = (m == 1) ? x1 : ((m == 2) ? x2 : x3);
            float4 pm, o;
            pm.x = xm.x + rm0*x0.x + rm1*x1.x + rm2*x2.x + rm3*x3.x;
            pm.y = xm.y + rm0*x0.y + rm1*x1.y + rm2*x2.y + rm3*x3.y;
            pm.z = xm.z + rm0*x0.z + rm1*x1.z + rm2*x2.z + rm3*x3.z;
            pm.w = xm.w + rm0*x0.w + rm1*x1.w + rm2*x2.w + rm3*x3.w;
            o.x = (pm.x + c * inn.x) * cs.x;
            o.y = (pm.y + c * inn.y) * cs.y;
            o.z = (pm.z + c * inn.z) * cs.z;
            o.w = (pm.w + c * inn.w) * cs.w;
            outv[(size_t)m * plane + tb] = o;
        }
    }
}

extern "C" void kernel_launch(void* const* d_in, const int* in_sizes, int n_in,
                              void* d_out, int out_size) {
    const float* hs   = (const float*)d_in[0];  // hidden_states [4,B,S,H]
    const float* act  = (const float*)d_in[1];  // activated [B,S,H]
    const float* rns  = (const float*)d_in[2];  // router_norm_scale [H]
    const float* rw   = (const float*)d_in[3];  // router_w [H,4]
    const float* pw   = (const float*)d_in[4];  // pred_w [4,16]
    const float* cw   = (const float*)d_in[5];  // corr_w [4,4]
    const float* cosc = (const float*)d_in[6];  // correct_output_scale [H]
    float* out = (float*)d_out;

    const int n_tokens = in_sizes[1] / HID;     // B*S = 8192
    const int grid = 304;                       // ~2 CTAs/SM on 152-SM GB300
    altup_kernel<<<grid, NTHREADS>>>(hs, act, rns, rw, pw, cw, cosc, out, n_tokens);
}